// round 1
// baseline (speedup 1.0000x reference)
#include <cuda_runtime.h>
#include <cuda_bf16.h>

#define N_NODES 100000
#define D 128

// Scratch (allocation-free rule: __device__ globals)
__device__ __align__(128) float g_msg[(size_t)N_NODES * D];  // 51.2 MB neighbor sums
__device__ __align__(128) float g_h[(size_t)N_NODES * D];    // 51.2 MB layer-0 output

// ---------------------------------------------------------------------------
// Scatter: one warp per edge. Lane l handles 4 floats (float4) of the 128-dim
// feature. Gather feat[src] (L2-resident), vector atomic-add into msg[dst]
// via red.global.add.v4.f32 (single 128-bit RED per lane).
// ---------------------------------------------------------------------------
__global__ void __launch_bounds__(256) scatter_kernel(
    const float* __restrict__ feat,
    const int*   __restrict__ src,
    const int*   __restrict__ dst,
    float*       __restrict__ msg,
    int n_edges)
{
    int warp = (blockIdx.x * 256 + threadIdx.x) >> 5;
    int lane = threadIdx.x & 31;
    if (warp >= n_edges) return;
    int s = __ldg(src + warp);
    int d = __ldg(dst + warp);
    const float4 v = *reinterpret_cast<const float4*>(feat + (size_t)s * D + lane * 4);
    float* p = msg + (size_t)d * D + lane * 4;
    asm volatile("red.global.add.v4.f32 [%0], {%1, %2, %3, %4};"
                 :: "l"(p), "f"(v.x), "f"(v.y), "f"(v.z), "f"(v.w) : "memory");
}

// ---------------------------------------------------------------------------
// Fused dual-GEMM:  Out = A @ Wself + (Msg * inv_deg) @ Wneigh + bias
// treated as one K=256 GEMM with concatenated A' = [A | Msg*inv_deg] and
// W' = [Wself ; Wneigh]. Tile: 64 rows x 128 cols (full N) per CTA,
// 256 threads, each thread: 8 rows (stride 8) x 4 cols (stride 32).
// A whole warp owns complete rows -> LN is a warp shfl-reduce (FUSE_LN).
// ---------------------------------------------------------------------------
template <bool FUSE_LN>
__global__ void __launch_bounds__(256) sage_gemm_kernel(
    const float* __restrict__ A,       // [N,128] self input
    const float* __restrict__ Msg,     // [N,128] neighbor sums
    const float* __restrict__ Wself,   // [128,128] row-major (k,c)
    const float* __restrict__ Wneigh,  // [128,128]
    const float* __restrict__ bias,    // [128]
    const int*   __restrict__ in_deg,  // [N]
    const float* __restrict__ ln_g,    // [128]
    const float* __restrict__ ln_b,    // [128]
    float*       __restrict__ Out)     // [N,128]
{
    __shared__ float As[64 * 16];    // 4 KB   A chunk  [64 rows x 16 k]
    __shared__ float Ws[16 * 128];   // 8 KB   W chunk  [16 k x 128 cols]
    __shared__ float sInv[64];

    const int t    = threadIdx.x;
    const int tx   = t & 31;         // lane -> base column
    const int ty   = t >> 5;         // warp -> base row
    const int row0 = blockIdx.x * 64;

    // inv_deg for this CTA's rows
    if (t < 64) {
        int grow = row0 + t;
        int dg = (grow < N_NODES) ? in_deg[grow] : 1;
        sInv[t] = 1.0f / (float)max(dg, 1);
    }
    __syncthreads();

    const int lr  = t >> 2;          // local row this thread loads (A chunk)
    const int lk4 = (t & 3) << 2;    // k offset within chunk (float4)

    float acc[8][4];
#pragma unroll
    for (int j = 0; j < 8; ++j)
#pragma unroll
        for (int c = 0; c < 4; ++c) acc[j][c] = 0.0f;

#pragma unroll 1
    for (int kc = 0; kc < 16; ++kc) {
        const int k0 = kc * 16;

        // ---- load A chunk (64x16) : one float4 per thread ----
        float4 a4 = make_float4(0.f, 0.f, 0.f, 0.f);
        {
            int grow = row0 + lr;
            if (grow < N_NODES) {
                if (k0 < 128) {
                    a4 = *reinterpret_cast<const float4*>(
                        A + (size_t)grow * 128 + (k0 + lk4));
                } else {
                    a4 = *reinterpret_cast<const float4*>(
                        Msg + (size_t)grow * 128 + (k0 - 128 + lk4));
                    float s = sInv[lr];
                    a4.x *= s; a4.y *= s; a4.z *= s; a4.w *= s;
                }
            }
        }
        *reinterpret_cast<float4*>(As + lr * 16 + lk4) = a4;

        // ---- load W chunk (16x128) : two float4 per thread ----
        {
            const float* Wsrc = (k0 < 128) ? Wself : Wneigh;
            const int kbase   = (k0 < 128) ? k0 : (k0 - 128);
#pragma unroll
            for (int i = 0; i < 2; ++i) {
                int idx = t + i * 256;          // 0..511 float4 slots
                int kk  = idx >> 5;             // 0..15
                int c4  = (idx & 31) << 2;      // 0..124 step 4
                *reinterpret_cast<float4*>(Ws + kk * 128 + c4) =
                    *reinterpret_cast<const float4*>(Wsrc + (size_t)(kbase + kk) * 128 + c4);
            }
        }
        __syncthreads();

        // ---- compute ----
#pragma unroll
        for (int kk = 0; kk < 16; ++kk) {
            float w0 = Ws[kk * 128 + tx];
            float w1 = Ws[kk * 128 + tx + 32];
            float w2 = Ws[kk * 128 + tx + 64];
            float w3 = Ws[kk * 128 + tx + 96];
#pragma unroll
            for (int j = 0; j < 8; ++j) {
                float a = As[(ty + j * 8) * 16 + kk];   // broadcast within warp
                acc[j][0] = fmaf(a, w0, acc[j][0]);
                acc[j][1] = fmaf(a, w1, acc[j][1]);
                acc[j][2] = fmaf(a, w2, acc[j][2]);
                acc[j][3] = fmaf(a, w3, acc[j][3]);
            }
        }
        __syncthreads();
    }

    // ---- epilogue ----
    float bia[4], lg[4], lb[4];
#pragma unroll
    for (int c = 0; c < 4; ++c) {
        int col = tx + 32 * c;
        bia[c] = bias[col];
        if (FUSE_LN) { lg[c] = ln_g[col]; lb[c] = ln_b[col]; }
    }

#pragma unroll
    for (int j = 0; j < 8; ++j) {
        int lrow = ty + j * 8;
        int grow = row0 + lrow;
        float v[4];
#pragma unroll
        for (int c = 0; c < 4; ++c) v[c] = acc[j][c] + bia[c];

        if (FUSE_LN) {
            // warp owns the full 128-col row: reduce across lanes
            float s = v[0] + v[1] + v[2] + v[3];
#pragma unroll
            for (int o = 16; o > 0; o >>= 1) s += __shfl_xor_sync(0xffffffffu, s, o);
            float mu = s * (1.0f / 128.0f);
            float d2 = 0.f;
#pragma unroll
            for (int c = 0; c < 4; ++c) { float dd = v[c] - mu; d2 += dd * dd; }
#pragma unroll
            for (int o = 16; o > 0; o >>= 1) d2 += __shfl_xor_sync(0xffffffffu, d2, o);
            float rstd = rsqrtf(d2 * (1.0f / 128.0f) + 1e-5f);
#pragma unroll
            for (int c = 0; c < 4; ++c) {
                float y = (v[c] - mu) * rstd * lg[c] + lb[c];
                v[c] = fmaxf(y, 0.0f);   // ReLU
            }
        }

        if (grow < N_NODES) {
#pragma unroll
            for (int c = 0; c < 4; ++c)
                Out[(size_t)grow * 128 + tx + 32 * c] = v[c];
        }
    }
}

// ---------------------------------------------------------------------------
// Launch
// Inputs (metadata order): feat, W_self0, W_neigh0, b0, W_self1, W_neigh1,
//                          b1, ln_g, ln_b, edge_src, edge_dst, in_deg
// ---------------------------------------------------------------------------
extern "C" void kernel_launch(void* const* d_in, const int* in_sizes, int n_in,
                              void* d_out, int out_size)
{
    const float* feat = (const float*)d_in[0];
    const float* Ws0  = (const float*)d_in[1];
    const float* Wn0  = (const float*)d_in[2];
    const float* b0   = (const float*)d_in[3];
    const float* Ws1  = (const float*)d_in[4];
    const float* Wn1  = (const float*)d_in[5];
    const float* b1   = (const float*)d_in[6];
    const float* lng  = (const float*)d_in[7];
    const float* lnb  = (const float*)d_in[8];
    const int*   esrc = (const int*)d_in[9];
    const int*   edst = (const int*)d_in[10];
    const int*   indeg= (const int*)d_in[11];
    const int n_edges = in_sizes[9];

    float *msg = nullptr, *h = nullptr;
    cudaGetSymbolAddress((void**)&msg, g_msg);
    cudaGetSymbolAddress((void**)&h,   g_h);

    const size_t msg_bytes = (size_t)N_NODES * D * sizeof(float);
    const int scat_blocks  = (n_edges + 7) / 8;          // 8 warps (edges) per CTA
    const int gemm_blocks  = (N_NODES + 63) / 64;

    // Layer 0
    cudaMemsetAsync(msg, 0, msg_bytes, 0);
    scatter_kernel<<<scat_blocks, 256>>>(feat, esrc, edst, msg, n_edges);
    sage_gemm_kernel<true><<<gemm_blocks, 256>>>(
        feat, msg, Ws0, Wn0, b0, indeg, lng, lnb, h);

    // Layer 1
    cudaMemsetAsync(msg, 0, msg_bytes, 0);
    scatter_kernel<<<scat_blocks, 256>>>(h, esrc, edst, msg, n_edges);
    sage_gemm_kernel<false><<<gemm_blocks, 256>>>(
        h, msg, Ws1, Wn1, b1, indeg, lng, lnb, (float*)d_out);
}

// round 2
// speedup vs baseline: 1.3887x; 1.3887x over previous
#include <cuda_runtime.h>
#include <cuda_bf16.h>

#define N_NODES 100000
#define N_EDGES_MAX 1600000
#define D 128

// ---------------------------------------------------------------------------
// Scratch (__device__ globals: allocation-free rule)
// ---------------------------------------------------------------------------
__device__ __align__(128) float g_msg[(size_t)N_NODES * D];   // 51.2 MB
__device__ __align__(128) float g_h[(size_t)N_NODES * D];     // 51.2 MB
__device__ __align__(128) int   g_deg[N_NODES];
__device__ __align__(128) int   g_off[N_NODES];
__device__ __align__(128) int   g_cur[N_NODES];
__device__ __align__(128) int   g_bsums[1024];
__device__ __align__(128) int   g_csr[N_EDGES_MAX];

// packed fp32x2 FMA (sm_103a; ptxas never emits this from C++)
#define FMA_F32X2(d, a, b) \
    asm("fma.rn.f32x2 %0, %1, %2, %0;" : "+l"(d) : "l"(a), "l"(b))
#define UNPACK_F32X2(lo, hi, in) \
    asm("mov.b64 {%0, %1}, %2;" : "=f"(lo), "=f"(hi) : "l"(in))

// ---------------------------------------------------------------------------
// CSR build: histogram -> block scan -> fill
// ---------------------------------------------------------------------------
__global__ void hist_kernel(const int* __restrict__ dst, int* __restrict__ deg,
                            int n_edges)
{
    int i = blockIdx.x * blockDim.x + threadIdx.x;
    if (i < n_edges) atomicAdd(deg + dst[i], 1);
}

__global__ void scan1_kernel(const int* __restrict__ deg, int* __restrict__ out,
                             int* __restrict__ bsums)
{
    __shared__ int sh[1024];
    int t = threadIdx.x;
    int i = blockIdx.x * 1024 + t;
    int v = (i < N_NODES) ? deg[i] : 0;
    sh[t] = v;
    __syncthreads();
#pragma unroll
    for (int off = 1; off < 1024; off <<= 1) {
        int x = 0;
        if (t >= off) x = sh[t - off];
        __syncthreads();
        if (t >= off) sh[t] += x;
        __syncthreads();
    }
    if (i < N_NODES) out[i] = sh[t] - v;           // exclusive (within block)
    if (t == 1023) bsums[blockIdx.x] = sh[1023];   // block total
}

__global__ void scan2_kernel(int* __restrict__ bsums, int nb)
{
    __shared__ int sh[1024];
    int t = threadIdx.x;
    int v = (t < nb) ? bsums[t] : 0;
    sh[t] = v;
    __syncthreads();
#pragma unroll
    for (int off = 1; off < 1024; off <<= 1) {
        int x = 0;
        if (t >= off) x = sh[t - off];
        __syncthreads();
        if (t >= off) sh[t] += x;
        __syncthreads();
    }
    if (t < nb) bsums[t] = sh[t] - v;              // exclusive
}

__global__ void scan3_kernel(int* __restrict__ off, int* __restrict__ cur,
                             const int* __restrict__ bsums)
{
    int i = blockIdx.x * 1024 + threadIdx.x;
    if (i < N_NODES) {
        int o = off[i] + bsums[blockIdx.x];
        off[i] = o;
        cur[i] = o;
    }
}

__global__ void fill_kernel(const int* __restrict__ src, const int* __restrict__ dst,
                            int* __restrict__ cur, int* __restrict__ csr, int n_edges)
{
    int i = blockIdx.x * blockDim.x + threadIdx.x;
    if (i < n_edges) {
        int pos = atomicAdd(cur + dst[i], 1);
        csr[pos] = src[i];
    }
}

// ---------------------------------------------------------------------------
// Aggregate: one warp per node. Lane handles float4 (4 of 128 dims).
// msg[n] = (sum over incoming src of feat[src]) * 1/max(in_deg[n],1)
// No atomics: reads L2-resident features, writes each row exactly once.
// ---------------------------------------------------------------------------
__global__ void __launch_bounds__(256) aggregate_kernel(
    const float* __restrict__ feat,
    const int*   __restrict__ csr,
    const int*   __restrict__ off,
    const int*   __restrict__ deg,
    const int*   __restrict__ in_deg,
    float*       __restrict__ msg)
{
    int node = (blockIdx.x * 256 + threadIdx.x) >> 5;
    int lane = threadIdx.x & 31;
    if (node >= N_NODES) return;

    int beg = __ldg(off + node);
    int cnt = __ldg(deg + node);

    float4 acc = make_float4(0.f, 0.f, 0.f, 0.f);
    int i = 0;
    for (; i + 4 <= cnt; i += 4) {
        int s0 = __ldg(csr + beg + i + 0);
        int s1 = __ldg(csr + beg + i + 1);
        int s2 = __ldg(csr + beg + i + 2);
        int s3 = __ldg(csr + beg + i + 3);
        float4 v0 = *reinterpret_cast<const float4*>(feat + (size_t)s0 * D + lane * 4);
        float4 v1 = *reinterpret_cast<const float4*>(feat + (size_t)s1 * D + lane * 4);
        float4 v2 = *reinterpret_cast<const float4*>(feat + (size_t)s2 * D + lane * 4);
        float4 v3 = *reinterpret_cast<const float4*>(feat + (size_t)s3 * D + lane * 4);
        acc.x += v0.x + v1.x + v2.x + v3.x;
        acc.y += v0.y + v1.y + v2.y + v3.y;
        acc.z += v0.z + v1.z + v2.z + v3.z;
        acc.w += v0.w + v1.w + v2.w + v3.w;
    }
    for (; i < cnt; ++i) {
        int s = __ldg(csr + beg + i);
        float4 v = *reinterpret_cast<const float4*>(feat + (size_t)s * D + lane * 4);
        acc.x += v.x; acc.y += v.y; acc.z += v.z; acc.w += v.w;
    }

    float inv = 1.0f / (float)max(__ldg(in_deg + node), 1);
    acc.x *= inv; acc.y *= inv; acc.z *= inv; acc.w *= inv;
    *reinterpret_cast<float4*>(msg + (size_t)node * D + lane * 4) = acc;
}

// ---------------------------------------------------------------------------
// Fused dual-GEMM with packed fp32x2 math:
//   Out = A @ Wself + Msg @ Wneigh + bias   (Msg already scaled by inv_deg)
// K=256 concat GEMM. Tile 64 rows x 128 cols per CTA, 256 threads.
// Thread: 8 rows x 4 cols as 8x2 packed f32x2 accumulators.
// SMEM: As2 = A chunk with duplicated (a,a) pairs; Wp = W chunk permuted so
// each lane's 4 columns are contiguous (one conflict-free LDS.128 = 2 w-pairs).
// Warp owns complete rows -> LN fused as shfl reduce.
// ---------------------------------------------------------------------------
#define AS_STRIDE 36   // floats per row in As2 (padded to kill STS conflicts)

template <bool FUSE_LN>
__global__ void __launch_bounds__(256) sage_gemm_kernel(
    const float* __restrict__ A,       // [N,128]
    const float* __restrict__ Msg,     // [N,128]
    const float* __restrict__ Wself,   // [128,128] row-major (k,c)
    const float* __restrict__ Wneigh,  // [128,128]
    const float* __restrict__ bias,    // [128]
    const float* __restrict__ ln_g,    // [128]
    const float* __restrict__ ln_b,    // [128]
    float*       __restrict__ Out)     // [N,128]
{
    __shared__ __align__(16) float As2[64 * AS_STRIDE];  // dup pairs: row*36 + kk*2
    __shared__ __align__(16) float Wp[16 * 128];         // permuted: kk*128 + lane*4 + g

    const int t    = threadIdx.x;
    const int tx   = t & 31;
    const int ty   = t >> 5;
    const int row0 = blockIdx.x * 64;

    const int lr  = t >> 2;          // local row this thread loads
    const int lk4 = (t & 3) << 2;    // k offset (float4) within 16-k chunk

    unsigned long long acc[8][2];
#pragma unroll
    for (int j = 0; j < 8; ++j) { acc[j][0] = 0ull; acc[j][1] = 0ull; }

#pragma unroll 1
    for (int kc = 0; kc < 16; ++kc) {
        const int k0 = kc * 16;

        // ---- A chunk: load float4, store duplicated pairs ----
        float4 a4 = make_float4(0.f, 0.f, 0.f, 0.f);
        {
            int grow = row0 + lr;
            if (grow < N_NODES) {
                const float* Asrc = (k0 < 128) ? A : Msg;
                int kb = (k0 < 128) ? k0 : (k0 - 128);
                a4 = *reinterpret_cast<const float4*>(Asrc + (size_t)grow * 128 + kb + lk4);
            }
        }
        *reinterpret_cast<float4*>(As2 + lr * AS_STRIDE + lk4 * 2) =
            make_float4(a4.x, a4.x, a4.y, a4.y);
        *reinterpret_cast<float4*>(As2 + lr * AS_STRIDE + lk4 * 2 + 4) =
            make_float4(a4.z, a4.z, a4.w, a4.w);

        // ---- W chunk: load row-major, store permuted ----
        {
            const float* Wsrc = (k0 < 128) ? Wself : Wneigh;
            const int kbase   = (k0 < 128) ? k0 : (k0 - 128);
#pragma unroll
            for (int i = 0; i < 2; ++i) {
                int idx = t + i * 256;          // 512 float4 slots
                int kk  = idx >> 5;             // 0..15
                int c4  = (idx & 31) << 2;      // col base 0..124
                float4 w = *reinterpret_cast<const float4*>(
                    Wsrc + (size_t)(kbase + kk) * 128 + c4);
                int g  = c4 >> 5;               // column group 0..3
                int l0 = c4 & 31;               // target lane base
                Wp[kk * 128 + (l0 + 0) * 4 + g] = w.x;
                Wp[kk * 128 + (l0 + 1) * 4 + g] = w.y;
                Wp[kk * 128 + (l0 + 2) * 4 + g] = w.z;
                Wp[kk * 128 + (l0 + 3) * 4 + g] = w.w;
            }
        }
        __syncthreads();

        // ---- compute: 16 k as 8 kk-pairs ----
#pragma unroll
        for (int m = 0; m < 8; ++m) {
            ulonglong2 wA = *reinterpret_cast<const ulonglong2*>(Wp + (2 * m) * 128 + tx * 4);
            ulonglong2 wB = *reinterpret_cast<const ulonglong2*>(Wp + (2 * m + 1) * 128 + tx * 4);
#pragma unroll
            for (int j = 0; j < 8; ++j) {
                ulonglong2 ap = *reinterpret_cast<const ulonglong2*>(
                    As2 + (ty + j * 8) * AS_STRIDE + m * 4);
                FMA_F32X2(acc[j][0], ap.x, wA.x);   // cols (tx, tx+32)
                FMA_F32X2(acc[j][1], ap.x, wA.y);   // cols (tx+64, tx+96)
                FMA_F32X2(acc[j][0], ap.y, wB.x);
                FMA_F32X2(acc[j][1], ap.y, wB.y);
            }
        }
        __syncthreads();
    }

    // ---- epilogue ----
    float bia[4], lg[4], lb[4];
#pragma unroll
    for (int c = 0; c < 4; ++c) {
        int col = tx + 32 * c;
        bia[c] = bias[col];
        if (FUSE_LN) { lg[c] = ln_g[col]; lb[c] = ln_b[col]; }
    }

#pragma unroll
    for (int j = 0; j < 8; ++j) {
        int grow = row0 + ty + j * 8;
        float v[4];
        UNPACK_F32X2(v[0], v[1], acc[j][0]);
        UNPACK_F32X2(v[2], v[3], acc[j][1]);
#pragma unroll
        for (int c = 0; c < 4; ++c) v[c] += bia[c];

        if (FUSE_LN) {
            float s = v[0] + v[1] + v[2] + v[3];
#pragma unroll
            for (int o = 16; o > 0; o >>= 1) s += __shfl_xor_sync(0xffffffffu, s, o);
            float mu = s * (1.0f / 128.0f);
            float d2 = 0.f;
#pragma unroll
            for (int c = 0; c < 4; ++c) { float dd = v[c] - mu; d2 += dd * dd; }
#pragma unroll
            for (int o = 16; o > 0; o >>= 1) d2 += __shfl_xor_sync(0xffffffffu, d2, o);
            float rstd = rsqrtf(d2 * (1.0f / 128.0f) + 1e-5f);
#pragma unroll
            for (int c = 0; c < 4; ++c) {
                float y = (v[c] - mu) * rstd * lg[c] + lb[c];
                v[c] = fmaxf(y, 0.0f);
            }
        }

        if (grow < N_NODES) {
#pragma unroll
            for (int c = 0; c < 4; ++c)
                Out[(size_t)grow * 128 + tx + 32 * c] = v[c];
        }
    }
}

// ---------------------------------------------------------------------------
// Launch.  Inputs: feat, W_self0, W_neigh0, b0, W_self1, W_neigh1, b1,
//                  ln_g, ln_b, edge_src, edge_dst, in_deg
// ---------------------------------------------------------------------------
extern "C" void kernel_launch(void* const* d_in, const int* in_sizes, int n_in,
                              void* d_out, int out_size)
{
    const float* feat = (const float*)d_in[0];
    const float* Ws0  = (const float*)d_in[1];
    const float* Wn0  = (const float*)d_in[2];
    const float* b0   = (const float*)d_in[3];
    const float* Ws1  = (const float*)d_in[4];
    const float* Wn1  = (const float*)d_in[5];
    const float* b1   = (const float*)d_in[6];
    const float* lng  = (const float*)d_in[7];
    const float* lnb  = (const float*)d_in[8];
    const int*   esrc = (const int*)d_in[9];
    const int*   edst = (const int*)d_in[10];
    const int*   indeg= (const int*)d_in[11];
    const int n_edges = in_sizes[9];

    float *msg = nullptr, *h = nullptr;
    int *deg = nullptr, *off = nullptr, *cur = nullptr, *bsums = nullptr, *csr = nullptr;
    cudaGetSymbolAddress((void**)&msg,   g_msg);
    cudaGetSymbolAddress((void**)&h,     g_h);
    cudaGetSymbolAddress((void**)&deg,   g_deg);
    cudaGetSymbolAddress((void**)&off,   g_off);
    cudaGetSymbolAddress((void**)&cur,   g_cur);
    cudaGetSymbolAddress((void**)&bsums, g_bsums);
    cudaGetSymbolAddress((void**)&csr,   g_csr);

    const int eb          = (n_edges + 255) / 256;
    const int nscan       = (N_NODES + 1023) / 1024;   // 98
    const int agg_blocks  = (N_NODES + 7) / 8;         // warp per node
    const int gemm_blocks = (N_NODES + 63) / 64;

    // ---- CSR build (graph shared by both layers) ----
    cudaMemsetAsync(deg, 0, N_NODES * sizeof(int), 0);
    hist_kernel<<<eb, 256>>>(edst, deg, n_edges);
    scan1_kernel<<<nscan, 1024>>>(deg, off, bsums);
    scan2_kernel<<<1, 1024>>>(bsums, nscan);
    scan3_kernel<<<nscan, 1024>>>(off, cur, bsums);
    fill_kernel<<<eb, 256>>>(esrc, edst, cur, csr, n_edges);

    // ---- Layer 0 ----
    aggregate_kernel<<<agg_blocks, 256>>>(feat, csr, off, deg, indeg, msg);
    sage_gemm_kernel<true><<<gemm_blocks, 256>>>(
        feat, msg, Ws0, Wn0, b0, lng, lnb, h);

    // ---- Layer 1 ----
    aggregate_kernel<<<agg_blocks, 256>>>(h, csr, off, deg, indeg, msg);
    sage_gemm_kernel<false><<<gemm_blocks, 256>>>(
        h, msg, Ws1, Wn1, b1, lng, lnb, (float*)d_out);
}

// round 5
// speedup vs baseline: 1.4310x; 1.0304x over previous
#include <cuda_runtime.h>
#include <cuda_bf16.h>
#include <cstdint>

#define N_NODES 100000
#define N_EDGES_MAX 1600000
#define D 128

// ---------------------------------------------------------------------------
// Scratch (__device__ globals: allocation-free rule)
// ---------------------------------------------------------------------------
__device__ __align__(128) float g_h[(size_t)N_NODES * D];     // 51.2 MB
__device__ __align__(128) int   g_deg[N_NODES];
__device__ __align__(128) int   g_off[N_NODES];
__device__ __align__(128) int   g_cur[N_NODES];
__device__ __align__(128) int   g_bsums[1024];
__device__ __align__(128) int   g_csr[N_EDGES_MAX];
// Pre-permuted weights: [layer][chunk kc 0..15][2048] in GEMM SMEM layout:
//   wperm[l][kc*2048 + kk*128 + lane*4 + g] = W'_l[kc*16+kk][g*32+lane]
// where W'_l = [Wself_l ; Wneigh_l] (K=256 concat)
__device__ __align__(16) float g_wperm[2 * 16 * 2048];

// packed fp32x2 FMA (sm_103a; ptxas never emits this from C++)
#define FMA_F32X2(d, a, b) \
    asm("fma.rn.f32x2 %0, %1, %2, %0;" : "+l"(d) : "l"(a), "l"(b))
#define UNPACK_F32X2(lo, hi, in) \
    asm("mov.b64 {%0, %1}, %2;" : "=f"(lo), "=f"(hi) : "l"(in))

// ---------------------------------------------------------------------------
// Weight prep: permute both layers' [Wself;Wneigh] into GEMM SMEM layout
// ---------------------------------------------------------------------------
__global__ void prep_w_kernel(const float* __restrict__ Ws0, const float* __restrict__ Wn0,
                              const float* __restrict__ Ws1, const float* __restrict__ Wn1)
{
    int gid = blockIdx.x * blockDim.x + threadIdx.x;   // 65536
    if (gid >= 2 * 16 * 2048) return;
    int l  = gid >> 15;
    int r  = gid & 32767;
    int kc = r >> 11;
    int p  = r & 2047;
    int kk = p >> 7;
    int q  = p & 127;
    int lane = q >> 2;
    int g    = q & 3;
    int c = g * 32 + lane;            // column 0..127
    int k = kc * 16 + kk;             // concat-k 0..255
    const float* Wsrc = (l == 0) ? ((k < 128) ? Ws0 : Wn0)
                                 : ((k < 128) ? Ws1 : Wn1);
    g_wperm[gid] = Wsrc[(size_t)(k & 127) * 128 + c];
}

// ---------------------------------------------------------------------------
// CSR build: histogram -> block scan -> fill
// ---------------------------------------------------------------------------
__global__ void hist_kernel(const int* __restrict__ dst, int* __restrict__ deg,
                            int n_edges)
{
    int i = blockIdx.x * blockDim.x + threadIdx.x;
    if (i < n_edges) atomicAdd(deg + dst[i], 1);
}

__global__ void scan1_kernel(const int* __restrict__ deg, int* __restrict__ out,
                             int* __restrict__ bsums)
{
    __shared__ int sh[1024];
    int t = threadIdx.x;
    int i = blockIdx.x * 1024 + t;
    int v = (i < N_NODES) ? deg[i] : 0;
    sh[t] = v;
    __syncthreads();
#pragma unroll
    for (int off = 1; off < 1024; off <<= 1) {
        int x = 0;
        if (t >= off) x = sh[t - off];
        __syncthreads();
        if (t >= off) sh[t] += x;
        __syncthreads();
    }
    if (i < N_NODES) out[i] = sh[t] - v;
    if (t == 1023) bsums[blockIdx.x] = sh[1023];
}

__global__ void scan2_kernel(int* __restrict__ bsums, int nb)
{
    __shared__ int sh[1024];
    int t = threadIdx.x;
    int v = (t < nb) ? bsums[t] : 0;
    sh[t] = v;
    __syncthreads();
#pragma unroll
    for (int off = 1; off < 1024; off <<= 1) {
        int x = 0;
        if (t >= off) x = sh[t - off];
        __syncthreads();
        if (t >= off) sh[t] += x;
        __syncthreads();
    }
    if (t < nb) bsums[t] = sh[t] - v;
}

__global__ void scan3_kernel(int* __restrict__ off, int* __restrict__ cur,
                             const int* __restrict__ bsums)
{
    int i = blockIdx.x * 1024 + threadIdx.x;
    if (i < N_NODES) {
        int o = off[i] + bsums[blockIdx.x];
        off[i] = o;
        cur[i] = o;
    }
}

__global__ void fill_kernel(const int* __restrict__ src, const int* __restrict__ dst,
                            int* __restrict__ cur, int* __restrict__ csr, int n_edges)
{
    int i = blockIdx.x * blockDim.x + threadIdx.x;
    if (i < n_edges) {
        int pos = atomicAdd(cur + dst[i], 1);
        csr[pos] = src[i];
    }
}

// ---------------------------------------------------------------------------
// FUSED layer kernel:
//   Phase 1 (aggregate): warp per row (8 rows/warp), gather-sum incoming
//     neighbor rows of A, scale by 1/max(in_deg,1), store to SMEM smsg.
//   Phase 2 (GEMM): Out = A @ Wself + smsg @ Wneigh + bias (K=256 concat,
//     packed f32x2 math), LN+ReLU fused for layer 0.
// Tile 64 rows x 128 cols, 256 threads. Thread: 8 rows x 4 cols (8x2 f32x2).
// Overlap of phases happens across resident CTAs.
// ---------------------------------------------------------------------------
#define AS_STRIDE 36     // floats per row in As2
#define MS_STRIDE 132    // floats per row in smsg (pad: 16B-aligned, low conflict)

template <bool FUSE_LN>
__global__ void __launch_bounds__(256) sage_fused_kernel(
    const float* __restrict__ A,       // [N,128] layer input
    const int*   __restrict__ csr,
    const int*   __restrict__ off,
    const int*   __restrict__ deg,
    const int*   __restrict__ in_deg,
    const float* __restrict__ Wp_g,    // pre-permuted weights [16*2048]
    const float* __restrict__ bias,
    const float* __restrict__ ln_g,
    const float* __restrict__ ln_b,
    float*       __restrict__ Out)     // [N,128]
{
    extern __shared__ __align__(16) float dynf[];
    float* smsg = dynf;                       // 64*132 = 8448 floats
    float* As2  = dynf + 64 * MS_STRIDE;      // 64*36  = 2304 floats
    float* Wp   = As2 + 64 * AS_STRIDE;       // 2048 floats
    __shared__ float sInv[64];

    const int t    = threadIdx.x;
    const int tx   = t & 31;
    const int ty   = t >> 5;
    const int row0 = blockIdx.x * 64;

    if (t < 64) {
        int grow = row0 + t;
        int dg = (grow < N_NODES) ? __ldg(in_deg + grow) : 1;
        sInv[t] = 1.0f / (float)max(dg, 1);
    }
    __syncthreads();

    // ================= Phase 1: aggregate 64 rows into smsg =================
    {
        const int lane = tx;
#pragma unroll 1
        for (int j = 0; j < 8; ++j) {
            int lr   = ty * 8 + j;
            int grow = row0 + lr;
            float4 acc = make_float4(0.f, 0.f, 0.f, 0.f);
            if (grow < N_NODES) {
                int beg = __ldg(off + grow);
                int cnt = __ldg(deg + grow);
                int i = 0;
                for (; i + 4 <= cnt; i += 4) {
                    int s0 = __ldg(csr + beg + i + 0);
                    int s1 = __ldg(csr + beg + i + 1);
                    int s2 = __ldg(csr + beg + i + 2);
                    int s3 = __ldg(csr + beg + i + 3);
                    float4 v0 = *reinterpret_cast<const float4*>(A + (size_t)s0 * D + lane * 4);
                    float4 v1 = *reinterpret_cast<const float4*>(A + (size_t)s1 * D + lane * 4);
                    float4 v2 = *reinterpret_cast<const float4*>(A + (size_t)s2 * D + lane * 4);
                    float4 v3 = *reinterpret_cast<const float4*>(A + (size_t)s3 * D + lane * 4);
                    acc.x += v0.x + v1.x + v2.x + v3.x;
                    acc.y += v0.y + v1.y + v2.y + v3.y;
                    acc.z += v0.z + v1.z + v2.z + v3.z;
                    acc.w += v0.w + v1.w + v2.w + v3.w;
                }
                for (; i < cnt; ++i) {
                    int s = __ldg(csr + beg + i);
                    float4 v = *reinterpret_cast<const float4*>(A + (size_t)s * D + lane * 4);
                    acc.x += v.x; acc.y += v.y; acc.z += v.z; acc.w += v.w;
                }
                float inv = sInv[lr];
                acc.x *= inv; acc.y *= inv; acc.z *= inv; acc.w *= inv;
            }
            *reinterpret_cast<float4*>(smsg + lr * MS_STRIDE + lane * 4) = acc;
        }
    }
    __syncthreads();

    // ================= Phase 2: K=256 f32x2 GEMM =================
    const int lr  = t >> 2;          // local row this thread loads (A chunk)
    const int lk4 = (t & 3) << 2;    // k offset (float4) within 16-k chunk

    unsigned long long acc[8][2];
#pragma unroll
    for (int j = 0; j < 8; ++j) { acc[j][0] = 0ull; acc[j][1] = 0ull; }

#pragma unroll 1
    for (int kc = 0; kc < 16; ++kc) {
        const int k0 = kc * 16;

        // ---- A chunk: global A (k<128) or SMEM smsg (k>=128); dup pairs ----
        float4 a4 = make_float4(0.f, 0.f, 0.f, 0.f);
        {
            int grow = row0 + lr;
            if (k0 < 128) {
                if (grow < N_NODES)
                    a4 = *reinterpret_cast<const float4*>(A + (size_t)grow * 128 + k0 + lk4);
            } else {
                a4 = *reinterpret_cast<const float4*>(smsg + lr * MS_STRIDE + (k0 - 128 + lk4));
            }
        }
        // ---- W chunk: straight copy of pre-permuted weights ----
        float4 w0 = *reinterpret_cast<const float4*>(Wp_g + kc * 2048 + t * 4);
        float4 w1 = *reinterpret_cast<const float4*>(Wp_g + kc * 2048 + (t + 256) * 4);

        __syncthreads();   // previous chunk's compute done before overwrite
        *reinterpret_cast<float4*>(As2 + lr * AS_STRIDE + lk4 * 2) =
            make_float4(a4.x, a4.x, a4.y, a4.y);
        *reinterpret_cast<float4*>(As2 + lr * AS_STRIDE + lk4 * 2 + 4) =
            make_float4(a4.z, a4.z, a4.w, a4.w);
        *reinterpret_cast<float4*>(Wp + t * 4)         = w0;
        *reinterpret_cast<float4*>(Wp + (t + 256) * 4) = w1;
        __syncthreads();

        // ---- compute: 16 k as 8 kk-pairs ----
#pragma unroll
        for (int m = 0; m < 8; ++m) {
            ulonglong2 wA = *reinterpret_cast<const ulonglong2*>(Wp + (2 * m) * 128 + tx * 4);
            ulonglong2 wB = *reinterpret_cast<const ulonglong2*>(Wp + (2 * m + 1) * 128 + tx * 4);
#pragma unroll
            for (int j = 0; j < 8; ++j) {
                ulonglong2 ap = *reinterpret_cast<const ulonglong2*>(
                    As2 + (ty + j * 8) * AS_STRIDE + m * 4);
                FMA_F32X2(acc[j][0], ap.x, wA.x);   // cols (tx, tx+32)
                FMA_F32X2(acc[j][1], ap.x, wA.y);   // cols (tx+64, tx+96)
                FMA_F32X2(acc[j][0], ap.y, wB.x);
                FMA_F32X2(acc[j][1], ap.y, wB.y);
            }
        }
    }

    // ================= Epilogue =================
    float bia[4], lg[4], lb[4];
#pragma unroll
    for (int c = 0; c < 4; ++c) {
        int col = tx + 32 * c;
        bia[c] = bias[col];
        if (FUSE_LN) { lg[c] = ln_g[col]; lb[c] = ln_b[col]; }
    }

#pragma unroll
    for (int j = 0; j < 8; ++j) {
        int grow = row0 + ty + j * 8;
        float v[4];
        UNPACK_F32X2(v[0], v[1], acc[j][0]);
        UNPACK_F32X2(v[2], v[3], acc[j][1]);
#pragma unroll
        for (int c = 0; c < 4; ++c) v[c] += bia[c];

        if (FUSE_LN) {
            float s = v[0] + v[1] + v[2] + v[3];
#pragma unroll
            for (int o = 16; o > 0; o >>= 1) s += __shfl_xor_sync(0xffffffffu, s, o);
            float mu = s * (1.0f / 128.0f);
            float d2 = 0.f;
#pragma unroll
            for (int c = 0; c < 4; ++c) { float dd = v[c] - mu; d2 += dd * dd; }
#pragma unroll
            for (int o = 16; o > 0; o >>= 1) d2 += __shfl_xor_sync(0xffffffffu, d2, o);
            float rstd = rsqrtf(d2 * (1.0f / 128.0f) + 1e-5f);
#pragma unroll
            for (int c = 0; c < 4; ++c) {
                float y = (v[c] - mu) * rstd * lg[c] + lb[c];
                v[c] = fmaxf(y, 0.0f);
            }
        }

        if (grow < N_NODES) {
#pragma unroll
            for (int c = 0; c < 4; ++c)
                Out[(size_t)grow * 128 + tx + 32 * c] = v[c];
        }
    }
}

// ---------------------------------------------------------------------------
// Launch.  Inputs: feat, W_self0, W_neigh0, b0, W_self1, W_neigh1, b1,
//                  ln_g, ln_b, edge_src, edge_dst, in_deg
// ---------------------------------------------------------------------------
extern "C" void kernel_launch(void* const* d_in, const int* in_sizes, int n_in,
                              void* d_out, int out_size)
{
    const float* feat = (const float*)d_in[0];
    const float* Ws0  = (const float*)d_in[1];
    const float* Wn0  = (const float*)d_in[2];
    const float* b0   = (const float*)d_in[3];
    const float* Ws1  = (const float*)d_in[4];
    const float* Wn1  = (const float*)d_in[5];
    const float* b1   = (const float*)d_in[6];
    const float* lng  = (const float*)d_in[7];
    const float* lnb  = (const float*)d_in[8];
    const int*   esrc = (const int*)d_in[9];
    const int*   edst = (const int*)d_in[10];
    const int*   indeg= (const int*)d_in[11];
    const int n_edges = in_sizes[9];

    float *h = nullptr, *wperm = nullptr;
    int *deg = nullptr, *off = nullptr, *cur = nullptr, *bsums = nullptr, *csr = nullptr;
    cudaGetSymbolAddress((void**)&h,     g_h);
    cudaGetSymbolAddress((void**)&deg,   g_deg);
    cudaGetSymbolAddress((void**)&off,   g_off);
    cudaGetSymbolAddress((void**)&cur,   g_cur);
    cudaGetSymbolAddress((void**)&bsums, g_bsums);
    cudaGetSymbolAddress((void**)&csr,   g_csr);
    cudaGetSymbolAddress((void**)&wperm, g_wperm);

    const int eb          = (n_edges + 255) / 256;
    const int nscan       = (N_NODES + 1023) / 1024;
    const int gemm_blocks = (N_NODES + 63) / 64;   // 1563
    const int dyn_smem    = (64 * MS_STRIDE + 64 * AS_STRIDE + 2048) * 4;  // 51200

    cudaFuncSetAttribute(sage_fused_kernel<true>,
                         cudaFuncAttributeMaxDynamicSharedMemorySize, dyn_smem);
    cudaFuncSetAttribute(sage_fused_kernel<false>,
                         cudaFuncAttributeMaxDynamicSharedMemorySize, dyn_smem);

    // ---- weight prep + CSR build (shared by both layers) ----
    prep_w_kernel<<<(2 * 16 * 2048 + 255) / 256, 256>>>(Ws0, Wn0, Ws1, Wn1);
    cudaMemsetAsync(deg, 0, N_NODES * sizeof(int), 0);
    hist_kernel<<<eb, 256>>>(edst, deg, n_edges);
    scan1_kernel<<<nscan, 1024>>>(deg, off, bsums);
    scan2_kernel<<<1, 1024>>>(bsums, nscan);
    scan3_kernel<<<nscan, 1024>>>(off, cur, bsums);
    fill_kernel<<<eb, 256>>>(esrc, edst, cur, csr, n_edges);

    // ---- Layer 0 (aggregate + GEMM + LN + ReLU fused) ----
    sage_fused_kernel<true><<<gemm_blocks, 256, dyn_smem>>>(
        feat, csr, off, deg, indeg, wperm, b0, lng, lnb, h);

    // ---- Layer 1 ----
    sage_fused_kernel<false><<<gemm_blocks, 256, dyn_smem>>>(
        h, csr, off, deg, indeg, wperm + 16 * 2048, b1, lng, lnb, (float*)d_out);
}